// round 13
// baseline (speedup 1.0000x reference)
#include <cuda_runtime.h>
#include <cuda_bf16.h>
#include <cuda_fp16.h>
#include <cstdint>

// Problem constants (fixed by the reference)
#define NVOX   131072
#define KVOL   27
#define PPK    65536
#define CIN    64
#define COUT   64
#define NTHREADS 128
#define TILES  4            // tiles per block, per-warp rolling double buffer

// ---------------------------------------------------------------------------
// Pre-converted fp16 operands:
//   g_in : in_feats as fp16, [NVOX][CIN]  (rows are 128B = 1 cache line)
//   g_Wh : weights as fp16, transposed + column-permuted [KVOL][64 phys n][CIN]
// Physical row p = 8j + c holds logical cout n = 16*(j>>1)+4*(c>>1)+2*(j&1)+(c&1)
// -> each MMA thread's 4 values from a physical tile pair cover 4 consecutive
//    couts (red.v4 epilogue straight from fragments).
// ---------------------------------------------------------------------------
__device__ __half g_in[NVOX * CIN];
__device__ __half g_Wh[KVOL * COUT * CIN];

// smem: B 8KB + A double buffer 2 x 16KB (4KB per warp per buffer)
#define SM_B     0
#define SM_A0    8192
#define SM_A1    24576
#define SM_TOTAL 40960

// ---------------------------------------------------------------------------
// PTX helpers (family-portable: cp.async sm_80+, ldmatrix sm_75+, red sm_90)
// ---------------------------------------------------------------------------
__device__ __forceinline__ uint32_t smem_u32(const void* p) {
    uint32_t a;
    asm("{ .reg .u64 t; cvta.to.shared.u64 t, %1; cvt.u32.u64 %0, t; }" : "=r"(a) : "l"(p));
    return a;
}

#define CP_ASYNC_16(dst, src) \
    asm volatile("cp.async.cg.shared.global [%0], [%1], 16;" :: "r"(dst), "l"(src))
#define CP_COMMIT() asm volatile("cp.async.commit_group;" ::: "memory")
#define CP_WAIT(n)  asm volatile("cp.async.wait_group %0;" :: "n"(n) : "memory")

__device__ __forceinline__ void ldsm_x4(uint32_t r[4], uint32_t addr) {
    asm volatile("ldmatrix.sync.aligned.m8n8.x4.shared.b16 {%0,%1,%2,%3}, [%4];"
                 : "=r"(r[0]), "=r"(r[1]), "=r"(r[2]), "=r"(r[3]) : "r"(addr));
}

__device__ __forceinline__ void mma_fp16(float d[4], const uint32_t a[4], const uint32_t b[2]) {
    asm volatile(
        "mma.sync.aligned.m16n8k16.row.col.f32.f16.f16.f32 "
        "{%0,%1,%2,%3}, {%4,%5,%6,%7}, {%8,%9}, {%0,%1,%2,%3};"
        : "+f"(d[0]), "+f"(d[1]), "+f"(d[2]), "+f"(d[3])
        : "r"(a[0]), "r"(a[1]), "r"(a[2]), "r"(a[3]), "r"(b[0]), "r"(b[1]));
}

__device__ __forceinline__ void red_add_v4(float* addr, float a, float b, float c, float d) {
    asm volatile("red.global.add.v4.f32 [%0], {%1, %2, %3, %4};"
                 :: "l"(addr), "f"(a), "f"(b), "f"(c), "f"(d) : "memory");
}

// ---------------------------------------------------------------------------
// Kernel 1: fused output-bias init + in_feats->fp16 convert + weight prep
// (blocks 0..26 additionally convert one k-offset of weights)
// ---------------------------------------------------------------------------
__global__ void init_prep_kernel(float4* __restrict__ out,
                                 const float4* __restrict__ bias,
                                 const float4* __restrict__ in_feats,
                                 const float* __restrict__ weights) {
    const int i = blockIdx.x * blockDim.x + threadIdx.x;
    out[i] = bias[i & 15];
    float4 v = in_feats[i];
    __half2 h01 = make_half2(__float2half_rn(v.x), __float2half_rn(v.y));
    __half2 h23 = make_half2(__float2half_rn(v.z), __float2half_rn(v.w));
    uint2 hv;
    hv.x = *(uint32_t*)&h01;  hv.y = *(uint32_t*)&h23;
    *(uint2*)(g_in + 4 * (size_t)i) = hv;

    if (blockIdx.x < KVOL) {
        const int koff = blockIdx.x;
        const float* W = weights + (size_t)koff * CIN * COUT;
        __half* wh = g_Wh + (size_t)koff * COUT * CIN;
        for (int o = threadIdx.x; o < COUT * CIN; o += blockDim.x) {
            const int p = o >> 6, kk = o & 63;
            const int j = p >> 3, c = p & 7;
            const int n = 16 * (j >> 1) + 4 * (c >> 1) + 2 * (j & 1) + (c & 1);
            wh[o] = __float2half_rn(W[kk * COUT + n]);
        }
    }
}

// ---------------------------------------------------------------------------
// Per-warp async gather of 32 rows (index value passed in, no memory dep)
// ---------------------------------------------------------------------------
__device__ __forceinline__ void gather32_async(
    uint32_t dst_base, int myidx, int l)
{
    const int chunk = l & 7, rsub = l >> 3;          // rsub 0..3
    const uint32_t coff = (uint32_t)chunk << 4;
    #pragma unroll
    for (int q = 0; q < 8; q++) {
        const int src = __shfl_sync(0xffffffffu, myidx, q * 4 + rsub);
        const int r = q * 4 + rsub;                  // local row 0..31
        const uint32_t off = r * 128 + (coff ^ ((r & 7) << 4));
        CP_ASYNC_16(dst_base + off, (const char*)(g_in + (size_t)src * CIN) + coff);
    }
}

// ---------------------------------------------------------------------------
// Kernel 2: warp-autonomous fp16 HMMA GEMM-scatter, 4-tile rolling pipeline.
//   Warp w owns rows [32w, 32w+32) of each tile; ONE block barrier total.
// ---------------------------------------------------------------------------
__global__ __launch_bounds__(NTHREADS, 5) void conv3d_tc_kernel(
    const int*   __restrict__ imap,       // [KVOL, PPK]
    const int*   __restrict__ omap,       // [KVOL, PPK]
    float*       __restrict__ out)        // [NVOX, COUT]
{
    extern __shared__ __align__(128) char smem[];
    const uint32_t smem_base = smem_u32(smem);
    const int tid = threadIdx.x;
    const int w = tid >> 5, l = tid & 31;
    const int k  = blockIdx.y;
    const int p0 = blockIdx.x * (128 * TILES);

    const uint32_t abuf[2] = { smem_base + SM_A0 + w * 4096,
                               smem_base + SM_A1 + w * 4096 };
    const int* imap_base = imap + k * PPK + p0 + 32 * w;

    // preload all tile indices (no LDG gating gather issue later)
    int idx[TILES];
    #pragma unroll
    for (int t = 0; t < TILES; t++)
        idx[t] = imap_base[128 * t + l];

    // ---- group 0: B staging + tile-0 gather; group 1: tile-1 gather ----
    {
        const char* bh = (const char*)(g_Wh + (size_t)k * COUT * CIN);
        #pragma unroll
        for (int i = 0; i < 4; i++) {
            const int u = tid + i * NTHREADS;
            const int n = u >> 3, c = u & 7;
            const uint32_t off = n * 128 + ((c ^ (n & 7)) << 4);
            CP_ASYNC_16(smem_base + SM_B + off, bh + u * 16);
        }
        gather32_async(abuf[0], idx[0], l);
        CP_COMMIT();
        gather32_async(abuf[1], idx[1], l);
        CP_COMMIT();
    }

    // ---- per-lane ldmatrix address components (warp-local rows) ----
    const int lr = l & 7;
    const int rAl = ((l >> 3) & 1) * 8 + lr;     // local A row, t=0 (+16 for t=1)
    const int gA  = l >> 4;
    const int sA  = rAl & 7;
    const int nB  = 8 * (l >> 4) + lr;
    const int gB  = (l >> 3) & 1;
    const int sB  = nB & 7;
    const int gid = l >> 2, tig = l & 3;

    // wait for group 0 (B + own tile 0); ONE barrier so B is visible.
    CP_WAIT(1);
    __syncthreads();

    #pragma unroll
    for (int t = 0; t < TILES; t++) {
        // ensure gather t complete (groups complete in commit order)
        if (t == 1 || t == 2)      CP_WAIT(1);
        else if (t == 3)           CP_WAIT(0);

        const uint32_t ab = abuf[t & 1];

        // omap rows for this tile (consumed at scatter, hidden by MMA)
        int orow[2][2];
        {
            const int obase = k * PPK + p0 + 128 * t + 32 * w + gid;
            #pragma unroll
            for (int tt = 0; tt < 2; tt++)
                #pragma unroll
                for (int h = 0; h < 2; h++)
                    orow[tt][h] = __ldg(omap + obase + 16 * tt + 8 * h);
        }

        float d[2][8][4];
        #pragma unroll
        for (int tt = 0; tt < 2; tt++)
            #pragma unroll
            for (int j = 0; j < 8; j++)
                #pragma unroll
                for (int x = 0; x < 4; x++)
                    d[tt][j][x] = 0.0f;

        // ---- K loop: 4 x k16 steps ----
        #pragma unroll
        for (int ks = 0; ks < 4; ks++) {
            const int kcA = 2 * ks + gA;
            const int kcB = 2 * ks + gB;
            const uint32_t offA  = rAl * 128 + ((kcA ^ sA) << 4);
            const uint32_t offB0 = nB * 128 + ((kcB ^ sB) << 4);

            uint32_t a[2][4];
            ldsm_x4(a[0], ab + offA);
            ldsm_x4(a[1], ab + offA + 16 * 128);

            uint32_t b[8][2];
            #pragma unroll
            for (int jj = 0; jj < 4; jj++) {
                uint32_t rr[4];
                ldsm_x4(rr, smem_base + SM_B + offB0 + jj * 16 * 128);
                b[2 * jj][0] = rr[0]; b[2 * jj][1] = rr[1];
                b[2 * jj + 1][0] = rr[2]; b[2 * jj + 1][1] = rr[3];
            }

            #pragma unroll
            for (int tt = 0; tt < 2; tt++)
                #pragma unroll
                for (int j = 0; j < 8; j++)
                    mma_fp16(d[tt][j], a[tt], b[j]);
        }

        // issue gather t+2 into this (now dead) buffer — overlaps epilogue
        // and the next tile's compute. LDSM reads above already hit smem.
        if (t + 2 < TILES) {
            gather32_async(ab, idx[t + 2], l);
            CP_COMMIT();
        }

        // ---- scatter-add epilogue: red.v4 straight from fragments ----
        #pragma unroll
        for (int tt = 0; tt < 2; tt++) {
            #pragma unroll
            for (int h = 0; h < 2; h++) {
                float* dst = out + (size_t)orow[tt][h] * COUT + 4 * tig;
                #pragma unroll
                for (int jp = 0; jp < 4; jp++)
                    red_add_v4(dst + 16 * jp,
                               d[tt][2 * jp][2 * h],     d[tt][2 * jp][2 * h + 1],
                               d[tt][2 * jp + 1][2 * h], d[tt][2 * jp + 1][2 * h + 1]);
            }
        }
    }
}

// ---------------------------------------------------------------------------
extern "C" void kernel_launch(void* const* d_in, const int* in_sizes, int n_in,
                              void* d_out, int out_size) {
    const float* in_feats = (const float*)d_in[0];
    const float* weights  = (const float*)d_in[1];
    const float* bias     = (const float*)d_in[2];
    const int*   imap     = (const int*)d_in[3];
    const int*   omap     = (const int*)d_in[4];
    float*       out      = (float*)d_out;

    cudaFuncSetAttribute(conv3d_tc_kernel,
                         cudaFuncAttributeMaxDynamicSharedMemorySize, SM_TOTAL);

    init_prep_kernel<<<NVOX * CIN / 4 / 256, 256>>>(
        (float4*)out, (const float4*)bias, (const float4*)in_feats, weights);

    dim3 grid(PPK / 128 / TILES, KVOL);
    conv3d_tc_kernel<<<grid, NTHREADS, SM_TOTAL>>>(imap, omap, out);
}

// round 14
// speedup vs baseline: 1.5514x; 1.5514x over previous
#include <cuda_runtime.h>
#include <cuda_bf16.h>
#include <cuda_fp16.h>
#include <cstdint>

// Problem constants (fixed by the reference)
#define NVOX   131072
#define KVOL   27
#define PPK    65536
#define CIN    64
#define COUT   64
#define NTHREADS 128
#define TILES  4            // tiles per block, per-warp rolling double buffer

// ---------------------------------------------------------------------------
// Pre-converted fp16 operands:
//   g_in : in_feats as fp16, [NVOX][CIN]  (rows are 128B = 1 cache line)
//   g_Wh : weights as fp16, transposed + column-permuted [KVOL][64 phys n][CIN]
// Physical row p = 8j + c holds logical cout n = 16*(j>>1)+4*(c>>1)+2*(j&1)+(c&1)
// -> each MMA thread's 4 values from a physical tile pair cover 4 consecutive
//    couts (red.v4 epilogue straight from fragments).
// ---------------------------------------------------------------------------
__device__ __half g_in[NVOX * CIN];
__device__ __half g_Wh[KVOL * COUT * CIN];

// smem: B 8KB + A double buffer 2 x 16KB (4KB per warp per buffer)
#define SM_B     0
#define SM_A0    8192
#define SM_A1    24576
#define SM_TOTAL 40960

// ---------------------------------------------------------------------------
// PTX helpers (family-portable: cp.async sm_80+, ldmatrix sm_75+, red sm_90)
// ---------------------------------------------------------------------------
__device__ __forceinline__ uint32_t smem_u32(const void* p) {
    uint32_t a;
    asm("{ .reg .u64 t; cvta.to.shared.u64 t, %1; cvt.u32.u64 %0, t; }" : "=r"(a) : "l"(p));
    return a;
}

#define CP_ASYNC_16(dst, src) \
    asm volatile("cp.async.cg.shared.global [%0], [%1], 16;" :: "r"(dst), "l"(src))
#define CP_COMMIT() asm volatile("cp.async.commit_group;" ::: "memory")
#define CP_WAIT(n)  asm volatile("cp.async.wait_group %0;" :: "n"(n) : "memory")

__device__ __forceinline__ void ldsm_x4(uint32_t r[4], uint32_t addr) {
    asm volatile("ldmatrix.sync.aligned.m8n8.x4.shared.b16 {%0,%1,%2,%3}, [%4];"
                 : "=r"(r[0]), "=r"(r[1]), "=r"(r[2]), "=r"(r[3]) : "r"(addr));
}

__device__ __forceinline__ void mma_fp16(float d[4], const uint32_t a[4], const uint32_t b[2]) {
    asm volatile(
        "mma.sync.aligned.m16n8k16.row.col.f32.f16.f16.f32 "
        "{%0,%1,%2,%3}, {%4,%5,%6,%7}, {%8,%9}, {%0,%1,%2,%3};"
        : "+f"(d[0]), "+f"(d[1]), "+f"(d[2]), "+f"(d[3])
        : "r"(a[0]), "r"(a[1]), "r"(a[2]), "r"(a[3]), "r"(b[0]), "r"(b[1]));
}

__device__ __forceinline__ void red_add_v4(float* addr, float a, float b, float c, float d) {
    asm volatile("red.global.add.v4.f32 [%0], {%1, %2, %3, %4};"
                 :: "l"(addr), "f"(a), "f"(b), "f"(c), "f"(d) : "memory");
}

// ---------------------------------------------------------------------------
// Kernel 1: fused output-bias init + in_feats->fp16 convert + weight prep
// ---------------------------------------------------------------------------
__global__ void init_prep_kernel(float4* __restrict__ out,
                                 const float4* __restrict__ bias,
                                 const float4* __restrict__ in_feats,
                                 const float* __restrict__ weights) {
    const int i = blockIdx.x * blockDim.x + threadIdx.x;
    out[i] = bias[i & 15];
    float4 v = in_feats[i];
    __half2 h01 = make_half2(__float2half_rn(v.x), __float2half_rn(v.y));
    __half2 h23 = make_half2(__float2half_rn(v.z), __float2half_rn(v.w));
    uint2 hv;
    hv.x = *(uint32_t*)&h01;  hv.y = *(uint32_t*)&h23;
    *(uint2*)(g_in + 4 * (size_t)i) = hv;

    if (blockIdx.x < KVOL) {
        const int koff = blockIdx.x;
        const float* W = weights + (size_t)koff * CIN * COUT;
        __half* wh = g_Wh + (size_t)koff * COUT * CIN;
        for (int o = threadIdx.x; o < COUT * CIN; o += blockDim.x) {
            const int p = o >> 6, kk = o & 63;
            const int j = p >> 3, c = p & 7;
            const int n = 16 * (j >> 1) + 4 * (c >> 1) + 2 * (j & 1) + (c & 1);
            wh[o] = __float2half_rn(W[kk * COUT + n]);
        }
    }
}

// ---------------------------------------------------------------------------
// Per-warp async gather of 32 rows (index value passed in, no memory dep)
// ---------------------------------------------------------------------------
__device__ __forceinline__ void gather32_async(
    uint32_t dst_base, int myidx, int l)
{
    const int chunk = l & 7, rsub = l >> 3;          // rsub 0..3
    const uint32_t coff = (uint32_t)chunk << 4;
    #pragma unroll
    for (int q = 0; q < 8; q++) {
        const int src = __shfl_sync(0xffffffffu, myidx, q * 4 + rsub);
        const int r = q * 4 + rsub;                  // local row 0..31
        const uint32_t off = r * 128 + (coff ^ ((r & 7) << 4));
        CP_ASYNC_16(dst_base + off, (const char*)(g_in + (size_t)src * CIN) + coff);
    }
}

// ---------------------------------------------------------------------------
// Kernel 2: warp-autonomous fp16 HMMA GEMM-scatter, 4-tile rolling pipeline.
//   Warp w owns rows [32w, 32w+32) of each tile; ONE block barrier total.
//   4 blocks/SM (NO forced 5 — that spilled accumulators in R13).
// ---------------------------------------------------------------------------
__global__ __launch_bounds__(NTHREADS, 4) void conv3d_tc_kernel(
    const int*   __restrict__ imap,       // [KVOL, PPK]
    const int*   __restrict__ omap,       // [KVOL, PPK]
    float*       __restrict__ out)        // [NVOX, COUT]
{
    extern __shared__ __align__(128) char smem[];
    const uint32_t smem_base = smem_u32(smem);
    const int tid = threadIdx.x;
    const int w = tid >> 5, l = tid & 31;
    const int k  = blockIdx.y;
    const int p0 = blockIdx.x * (128 * TILES);

    const uint32_t abuf[2] = { smem_base + SM_A0 + w * 4096,
                               smem_base + SM_A1 + w * 4096 };
    const int* imap_base = imap + k * PPK + p0 + 32 * w;

    // preload all tile indices (no LDG gating gather issue later)
    int idx[TILES];
    #pragma unroll
    for (int t = 0; t < TILES; t++)
        idx[t] = imap_base[128 * t + l];

    // ---- group 0: B staging + tile-0 gather; group 1: tile-1 gather ----
    {
        const char* bh = (const char*)(g_Wh + (size_t)k * COUT * CIN);
        #pragma unroll
        for (int i = 0; i < 4; i++) {
            const int u = tid + i * NTHREADS;
            const int n = u >> 3, c = u & 7;
            const uint32_t off = n * 128 + ((c ^ (n & 7)) << 4);
            CP_ASYNC_16(smem_base + SM_B + off, bh + u * 16);
        }
        gather32_async(abuf[0], idx[0], l);
        CP_COMMIT();
        gather32_async(abuf[1], idx[1], l);
        CP_COMMIT();
    }

    // ---- per-lane ldmatrix address components (warp-local rows) ----
    const int lr = l & 7;
    const int rAl = ((l >> 3) & 1) * 8 + lr;     // local A row, t=0 (+16 for t=1)
    const int gA  = l >> 4;
    const int sA  = rAl & 7;
    const int nB  = 8 * (l >> 4) + lr;
    const int gB  = (l >> 3) & 1;
    const int sB  = nB & 7;
    const int gid = l >> 2, tig = l & 3;

    // wait for group 0 (B + own tile 0); ONE barrier so B is visible.
    CP_WAIT(1);
    __syncthreads();

    #pragma unroll
    for (int t = 0; t < TILES; t++) {
        // ensure gather t complete (groups complete in commit order)
        if (t == 1 || t == 2)      CP_WAIT(1);
        else if (t == 3)           CP_WAIT(0);

        const uint32_t ab = abuf[t & 1];

        // omap rows for this tile (consumed at scatter, hidden by MMA)
        int orow[2][2];
        {
            const int obase = k * PPK + p0 + 128 * t + 32 * w + gid;
            #pragma unroll
            for (int tt = 0; tt < 2; tt++)
                #pragma unroll
                for (int h = 0; h < 2; h++)
                    orow[tt][h] = __ldg(omap + obase + 16 * tt + 8 * h);
        }

        float d[2][8][4];
        #pragma unroll
        for (int tt = 0; tt < 2; tt++)
            #pragma unroll
            for (int j = 0; j < 8; j++)
                #pragma unroll
                for (int x = 0; x < 4; x++)
                    d[tt][j][x] = 0.0f;

        // ---- K loop: 4 x k16 steps ----
        #pragma unroll
        for (int ks = 0; ks < 4; ks++) {
            const int kcA = 2 * ks + gA;
            const int kcB = 2 * ks + gB;
            const uint32_t offA  = rAl * 128 + ((kcA ^ sA) << 4);
            const uint32_t offB0 = nB * 128 + ((kcB ^ sB) << 4);

            uint32_t a[2][4];
            ldsm_x4(a[0], ab + offA);
            ldsm_x4(a[1], ab + offA + 16 * 128);

            uint32_t b[8][2];
            #pragma unroll
            for (int jj = 0; jj < 4; jj++) {
                uint32_t rr[4];
                ldsm_x4(rr, smem_base + SM_B + offB0 + jj * 16 * 128);
                b[2 * jj][0] = rr[0]; b[2 * jj][1] = rr[1];
                b[2 * jj + 1][0] = rr[2]; b[2 * jj + 1][1] = rr[3];
            }

            #pragma unroll
            for (int tt = 0; tt < 2; tt++)
                #pragma unroll
                for (int j = 0; j < 8; j++)
                    mma_fp16(d[tt][j], a[tt], b[j]);
        }

        // issue gather t+2 into this (now dead) buffer — overlaps epilogue
        // and the next tile's compute. LDSM reads above already hit smem.
        if (t + 2 < TILES) {
            gather32_async(ab, idx[t + 2], l);
            CP_COMMIT();
        }

        // ---- scatter-add epilogue: red.v4 straight from fragments ----
        #pragma unroll
        for (int tt = 0; tt < 2; tt++) {
            #pragma unroll
            for (int h = 0; h < 2; h++) {
                float* dst = out + (size_t)orow[tt][h] * COUT + 4 * tig;
                #pragma unroll
                for (int jp = 0; jp < 4; jp++)
                    red_add_v4(dst + 16 * jp,
                               d[tt][2 * jp][2 * h],     d[tt][2 * jp][2 * h + 1],
                               d[tt][2 * jp + 1][2 * h], d[tt][2 * jp + 1][2 * h + 1]);
            }
        }
    }
}

// ---------------------------------------------------------------------------
extern "C" void kernel_launch(void* const* d_in, const int* in_sizes, int n_in,
                              void* d_out, int out_size) {
    const float* in_feats = (const float*)d_in[0];
    const float* weights  = (const float*)d_in[1];
    const float* bias     = (const float*)d_in[2];
    const int*   imap     = (const int*)d_in[3];
    const int*   omap     = (const int*)d_in[4];
    float*       out      = (float*)d_out;

    cudaFuncSetAttribute(conv3d_tc_kernel,
                         cudaFuncAttributeMaxDynamicSharedMemorySize, SM_TOTAL);

    init_prep_kernel<<<NVOX * CIN / 4 / 256, 256>>>(
        (float4*)out, (const float4*)bias, (const float4*)in_feats, weights);

    dim3 grid(PPK / 128 / TILES, KVOL);
    conv3d_tc_kernel<<<grid, NTHREADS, SM_TOTAL>>>(imap, omap, out);
}

// round 15
// speedup vs baseline: 1.6709x; 1.0771x over previous
#include <cuda_runtime.h>
#include <cuda_bf16.h>
#include <cuda_fp16.h>
#include <cstdint>

// Problem constants (fixed by the reference)
#define NVOX   131072
#define KVOL   27
#define PPK    65536
#define CIN    64
#define COUT   64
#define NTHREADS 128
#define TILES  2            // tiles per block, per-warp double buffered (R12 optimum)

// ---------------------------------------------------------------------------
// Pre-converted fp16 operands:
//   g_in : in_feats as fp16, [NVOX][CIN]  (rows are 128B = 1 cache line)
//   g_Wh : weights as fp16, transposed + column-permuted [KVOL][64 phys n][CIN]
// Physical row p = 8j + c holds logical cout n = 16*(j>>1)+4*(c>>1)+2*(j&1)+(c&1)
// -> each MMA thread's 4 values from a physical tile pair cover 4 consecutive
//    couts (red.v4 epilogue straight from fragments).
// ---------------------------------------------------------------------------
__device__ __half g_in[NVOX * CIN];
__device__ __half g_Wh[KVOL * COUT * CIN];

// smem: B 8KB + A double buffer 2 x 16KB (4KB per warp per buffer)
#define SM_B     0
#define SM_A0    8192
#define SM_A1    24576
#define SM_TOTAL 40960

// ---------------------------------------------------------------------------
// PTX helpers (family-portable: cp.async sm_80+, ldmatrix sm_75+, red sm_90)
// ---------------------------------------------------------------------------
__device__ __forceinline__ uint32_t smem_u32(const void* p) {
    uint32_t a;
    asm("{ .reg .u64 t; cvta.to.shared.u64 t, %1; cvt.u32.u64 %0, t; }" : "=r"(a) : "l"(p));
    return a;
}

#define CP_ASYNC_16(dst, src) \
    asm volatile("cp.async.cg.shared.global [%0], [%1], 16;" :: "r"(dst), "l"(src))
#define CP_COMMIT() asm volatile("cp.async.commit_group;" ::: "memory")
#define CP_WAIT(n)  asm volatile("cp.async.wait_group %0;" :: "n"(n) : "memory")

__device__ __forceinline__ void ldsm_x4(uint32_t r[4], uint32_t addr) {
    asm volatile("ldmatrix.sync.aligned.m8n8.x4.shared.b16 {%0,%1,%2,%3}, [%4];"
                 : "=r"(r[0]), "=r"(r[1]), "=r"(r[2]), "=r"(r[3]) : "r"(addr));
}

__device__ __forceinline__ void mma_fp16(float d[4], const uint32_t a[4], const uint32_t b[2]) {
    asm volatile(
        "mma.sync.aligned.m16n8k16.row.col.f32.f16.f16.f32 "
        "{%0,%1,%2,%3}, {%4,%5,%6,%7}, {%8,%9}, {%0,%1,%2,%3};"
        : "+f"(d[0]), "+f"(d[1]), "+f"(d[2]), "+f"(d[3])
        : "r"(a[0]), "r"(a[1]), "r"(a[2]), "r"(a[3]), "r"(b[0]), "r"(b[1]));
}

__device__ __forceinline__ void red_add_v4(float* addr, float a, float b, float c, float d) {
    asm volatile("red.global.add.v4.f32 [%0], {%1, %2, %3, %4};"
                 :: "l"(addr), "f"(a), "f"(b), "f"(c), "f"(d) : "memory");
}

// ---------------------------------------------------------------------------
// Kernel 1: fused output-bias init + in_feats->fp16 convert + weight prep
// (blocks 0..26 additionally convert one k-offset of weights)
// ---------------------------------------------------------------------------
__global__ void init_prep_kernel(float4* __restrict__ out,
                                 const float4* __restrict__ bias,
                                 const float4* __restrict__ in_feats,
                                 const float* __restrict__ weights) {
    const int i = blockIdx.x * blockDim.x + threadIdx.x;
    out[i] = bias[i & 15];
    float4 v = in_feats[i];
    __half2 h01 = make_half2(__float2half_rn(v.x), __float2half_rn(v.y));
    __half2 h23 = make_half2(__float2half_rn(v.z), __float2half_rn(v.w));
    uint2 hv;
    hv.x = *(uint32_t*)&h01;  hv.y = *(uint32_t*)&h23;
    *(uint2*)(g_in + 4 * (size_t)i) = hv;

    if (blockIdx.x < KVOL) {
        const int koff = blockIdx.x;
        const float* W = weights + (size_t)koff * CIN * COUT;
        __half* wh = g_Wh + (size_t)koff * COUT * CIN;
        for (int o = threadIdx.x; o < COUT * CIN; o += blockDim.x) {
            const int p = o >> 6, kk = o & 63;
            const int j = p >> 3, c = p & 7;
            const int n = 16 * (j >> 1) + 4 * (c >> 1) + 2 * (j & 1) + (c & 1);
            wh[o] = __float2half_rn(W[kk * COUT + n]);
        }
    }
}

// ---------------------------------------------------------------------------
// Per-warp async gather of 32 rows into a warp-private 4KB buffer
// ---------------------------------------------------------------------------
__device__ __forceinline__ void gather32_async(
    uint32_t dst_base, const int* __restrict__ imap_rows, int l)
{
    const int myidx = imap_rows[l];
    const int chunk = l & 7, rsub = l >> 3;          // rsub 0..3
    const uint32_t coff = (uint32_t)chunk << 4;
    #pragma unroll
    for (int q = 0; q < 8; q++) {
        const int src = __shfl_sync(0xffffffffu, myidx, q * 4 + rsub);
        const int r = q * 4 + rsub;                  // local row 0..31
        const uint32_t off = r * 128 + (coff ^ ((r & 7) << 4));
        CP_ASYNC_16(dst_base + off, (const char*)(g_in + (size_t)src * CIN) + coff);
    }
}

// ---------------------------------------------------------------------------
// Kernel 2: warp-autonomous fp16 HMMA GEMM-scatter (R12 configuration).
//   Block = 2 tiles x 128 pairs. Warp w owns rows [32w, 32w+32) of each tile,
//   private A buffers, ONE block barrier total (for the shared B tile).
// ---------------------------------------------------------------------------
__global__ __launch_bounds__(NTHREADS, 4) void conv3d_tc_kernel(
    const int*   __restrict__ imap,       // [KVOL, PPK]
    const int*   __restrict__ omap,       // [KVOL, PPK]
    float*       __restrict__ out)        // [NVOX, COUT]
{
    extern __shared__ __align__(128) char smem[];
    const uint32_t smem_base = smem_u32(smem);
    const int tid = threadIdx.x;
    const int w = tid >> 5, l = tid & 31;
    const int k  = blockIdx.y;
    const int p0 = blockIdx.x * (128 * TILES);

    const uint32_t abuf0 = smem_base + SM_A0 + w * 4096;
    const uint32_t abuf1 = smem_base + SM_A1 + w * 4096;
    const int* imap_base = imap + k * PPK + p0 + 32 * w;

    // ---- group 0: B staging + warp's tile-0 gather ----
    {
        const char* bh = (const char*)(g_Wh + (size_t)k * COUT * CIN);
        #pragma unroll
        for (int i = 0; i < 4; i++) {
            const int u = tid + i * NTHREADS;
            const int n = u >> 3, c = u & 7;
            const uint32_t off = n * 128 + ((c ^ (n & 7)) << 4);
            CP_ASYNC_16(smem_base + SM_B + off, bh + u * 16);
        }
        gather32_async(abuf0, imap_base, l);
        CP_COMMIT();
    }
    // ---- group 1: warp's tile-1 gather ----
    gather32_async(abuf1, imap_base + 128, l);
    CP_COMMIT();

    // ---- per-lane ldmatrix address components (warp-local rows) ----
    const int lr = l & 7;
    const int rAl = ((l >> 3) & 1) * 8 + lr;     // local A row, t=0 (+16 for t=1)
    const int gA  = l >> 4;
    const int sA  = rAl & 7;                     // (+16 leaves &7 invariant)
    const int nB  = 8 * (l >> 4) + lr;
    const int gB  = (l >> 3) & 1;
    const int sB  = nB & 7;
    const int gid = l >> 2, tig = l & 3;

    // wait for group 0 (B + own tile 0), then ONE barrier so B (written by all
    // warps) is visible; no further block syncs — warps free-run.
    CP_WAIT(1);
    __syncthreads();

    #pragma unroll
    for (int t = 0; t < TILES; t++) {
        const uint32_t abuf = t ? abuf1 : abuf0;
        if (t == 1) CP_WAIT(0);                  // own tile-1 gather done

        // omap rows for this tile (consumed at scatter, hidden by MMA)
        int orow[2][2];
        {
            const int obase = k * PPK + p0 + 128 * t + 32 * w + gid;
            #pragma unroll
            for (int tt = 0; tt < 2; tt++)
                #pragma unroll
                for (int h = 0; h < 2; h++)
                    orow[tt][h] = __ldg(omap + obase + 16 * tt + 8 * h);
        }

        float d[2][8][4];
        #pragma unroll
        for (int tt = 0; tt < 2; tt++)
            #pragma unroll
            for (int j = 0; j < 8; j++)
                #pragma unroll
                for (int x = 0; x < 4; x++)
                    d[tt][j][x] = 0.0f;

        // ---- K loop: 4 x k16 steps ----
        #pragma unroll
        for (int ks = 0; ks < 4; ks++) {
            const int kcA = 2 * ks + gA;
            const int kcB = 2 * ks + gB;
            const uint32_t offA  = rAl * 128 + ((kcA ^ sA) << 4);
            const uint32_t offB0 = nB * 128 + ((kcB ^ sB) << 4);

            uint32_t a[2][4];
            ldsm_x4(a[0], abuf + offA);
            ldsm_x4(a[1], abuf + offA + 16 * 128);

            uint32_t b[8][2];
            #pragma unroll
            for (int jj = 0; jj < 4; jj++) {
                uint32_t rr[4];
                ldsm_x4(rr, smem_base + SM_B + offB0 + jj * 16 * 128);
                b[2 * jj][0] = rr[0]; b[2 * jj][1] = rr[1];
                b[2 * jj + 1][0] = rr[2]; b[2 * jj + 1][1] = rr[3];
            }

            #pragma unroll
            for (int tt = 0; tt < 2; tt++)
                #pragma unroll
                for (int j = 0; j < 8; j++)
                    mma_fp16(d[tt][j], a[tt], b[j]);
        }

        // ---- scatter-add epilogue: red.v4 straight from fragments ----
        #pragma unroll
        for (int tt = 0; tt < 2; tt++) {
            #pragma unroll
            for (int h = 0; h < 2; h++) {
                float* dst = out + (size_t)orow[tt][h] * COUT + 4 * tig;
                #pragma unroll
                for (int jp = 0; jp < 4; jp++)
                    red_add_v4(dst + 16 * jp,
                               d[tt][2 * jp][2 * h],     d[tt][2 * jp][2 * h + 1],
                               d[tt][2 * jp + 1][2 * h], d[tt][2 * jp + 1][2 * h + 1]);
            }
        }
    }
}

// ---------------------------------------------------------------------------
extern "C" void kernel_launch(void* const* d_in, const int* in_sizes, int n_in,
                              void* d_out, int out_size) {
    const float* in_feats = (const float*)d_in[0];
    const float* weights  = (const float*)d_in[1];
    const float* bias     = (const float*)d_in[2];
    const int*   imap     = (const int*)d_in[3];
    const int*   omap     = (const int*)d_in[4];
    float*       out      = (float*)d_out;

    cudaFuncSetAttribute(conv3d_tc_kernel,
                         cudaFuncAttributeMaxDynamicSharedMemorySize, SM_TOTAL);

    init_prep_kernel<<<NVOX * CIN / 4 / 256, 256>>>(
        (float4*)out, (const float4*)bias, (const float4*)in_feats, weights);

    dim3 grid(PPK / 128 / TILES, KVOL);
    conv3d_tc_kernel<<<grid, NTHREADS, SM_TOTAL>>>(imap, omap, out);
}

// round 16
// speedup vs baseline: 1.6725x; 1.0009x over previous
#include <cuda_runtime.h>
#include <cuda_bf16.h>
#include <cuda_fp16.h>
#include <cstdint>

// Problem constants (fixed by the reference)
#define NVOX   131072
#define KVOL   27
#define PPK    65536
#define CIN    64
#define COUT   64
#define NTHREADS 128
#define TILES  2            // tiles per block, per-warp double buffered (R12 optimum)

// ---------------------------------------------------------------------------
// Pre-converted fp16 operands:
//   g_in : in_feats as fp16, [NVOX][CIN]  (rows are 128B = 1 cache line)
//   g_Wh : weights as fp16, transposed + column-permuted [KVOL][64 phys n][CIN]
// Physical row p = 8j + c holds logical cout n = 16*(j>>1)+4*(c>>1)+2*(j&1)+(c&1)
// -> each MMA thread's 4 values from a physical tile pair cover 4 consecutive
//    couts (red.v4 epilogue straight from fragments).
// ---------------------------------------------------------------------------
__device__ __half g_in[NVOX * CIN];
__device__ __half g_Wh[KVOL * COUT * CIN];

// smem: B 8KB + A double buffer 2 x 16KB (4KB per warp per buffer)
#define SM_B     0
#define SM_A0    8192
#define SM_A1    24576
#define SM_TOTAL 40960

// ---------------------------------------------------------------------------
// PTX helpers (family-portable: cp.async sm_80+, ldmatrix sm_75+, red sm_90)
// ---------------------------------------------------------------------------
__device__ __forceinline__ uint32_t smem_u32(const void* p) {
    uint32_t a;
    asm("{ .reg .u64 t; cvta.to.shared.u64 t, %1; cvt.u32.u64 %0, t; }" : "=r"(a) : "l"(p));
    return a;
}

#define CP_ASYNC_16(dst, src) \
    asm volatile("cp.async.cg.shared.global [%0], [%1], 16;" :: "r"(dst), "l"(src))
#define CP_COMMIT() asm volatile("cp.async.commit_group;" ::: "memory")
#define CP_WAIT(n)  asm volatile("cp.async.wait_group %0;" :: "n"(n) : "memory")

__device__ __forceinline__ void ldsm_x4(uint32_t r[4], uint32_t addr) {
    asm volatile("ldmatrix.sync.aligned.m8n8.x4.shared.b16 {%0,%1,%2,%3}, [%4];"
                 : "=r"(r[0]), "=r"(r[1]), "=r"(r[2]), "=r"(r[3]) : "r"(addr));
}

__device__ __forceinline__ void mma_fp16(float d[4], const uint32_t a[4], const uint32_t b[2]) {
    asm volatile(
        "mma.sync.aligned.m16n8k16.row.col.f32.f16.f16.f32 "
        "{%0,%1,%2,%3}, {%4,%5,%6,%7}, {%8,%9}, {%0,%1,%2,%3};"
        : "+f"(d[0]), "+f"(d[1]), "+f"(d[2]), "+f"(d[3])
        : "r"(a[0]), "r"(a[1]), "r"(a[2]), "r"(a[3]), "r"(b[0]), "r"(b[1]));
}

__device__ __forceinline__ void red_add_v4(float* addr, float a, float b, float c, float d) {
    asm volatile("red.global.add.v4.f32 [%0], {%1, %2, %3, %4};"
                 :: "l"(addr), "f"(a), "f"(b), "f"(c), "f"(d) : "memory");
}

// ---------------------------------------------------------------------------
// Kernel 1: fused output-bias init + in_feats->fp16 convert + weight prep.
// ILP=4: each thread handles 4 strided float4 with independent load chains
// (the R15 version was 1 element/thread and latency-bound at 12.8us).
// ---------------------------------------------------------------------------
__global__ void init_prep_kernel(float4* __restrict__ out,
                                 const float4* __restrict__ bias,
                                 const float4* __restrict__ in_feats,
                                 const float* __restrict__ weights) {
    const int base = blockIdx.x * (blockDim.x * 4) + threadIdx.x;

    float4 v[4];
    #pragma unroll
    for (int j = 0; j < 4; j++)
        v[j] = in_feats[base + j * 256];          // 4 independent LDG.128

    #pragma unroll
    for (int j = 0; j < 4; j++) {
        const int i = base + j * 256;
        out[i] = bias[i & 15];

        __half2 h01 = make_half2(__float2half_rn(v[j].x), __float2half_rn(v[j].y));
        __half2 h23 = make_half2(__float2half_rn(v[j].z), __float2half_rn(v[j].w));
        uint2 hv;
        hv.x = *(uint32_t*)&h01;  hv.y = *(uint32_t*)&h23;
        *(uint2*)(g_in + 4 * (size_t)i) = hv;
    }

    // blocks 0..26: convert one k-offset of weights (transpose + permute)
    if (blockIdx.x < KVOL) {
        const int koff = blockIdx.x;
        const float* W = weights + (size_t)koff * CIN * COUT;
        __half* wh = g_Wh + (size_t)koff * COUT * CIN;
        for (int o = threadIdx.x; o < COUT * CIN; o += blockDim.x) {
            const int p = o >> 6, kk = o & 63;
            const int j = p >> 3, c = p & 7;
            const int n = 16 * (j >> 1) + 4 * (c >> 1) + 2 * (j & 1) + (c & 1);
            wh[o] = __float2half_rn(W[kk * COUT + n]);
        }
    }
}

// ---------------------------------------------------------------------------
// Per-warp async gather of 32 rows into a warp-private 4KB buffer
// ---------------------------------------------------------------------------
__device__ __forceinline__ void gather32_async(
    uint32_t dst_base, const int* __restrict__ imap_rows, int l)
{
    const int myidx = imap_rows[l];
    const int chunk = l & 7, rsub = l >> 3;          // rsub 0..3
    const uint32_t coff = (uint32_t)chunk << 4;
    #pragma unroll
    for (int q = 0; q < 8; q++) {
        const int src = __shfl_sync(0xffffffffu, myidx, q * 4 + rsub);
        const int r = q * 4 + rsub;                  // local row 0..31
        const uint32_t off = r * 128 + (coff ^ ((r & 7) << 4));
        CP_ASYNC_16(dst_base + off, (const char*)(g_in + (size_t)src * CIN) + coff);
    }
}

// ---------------------------------------------------------------------------
// Kernel 2: warp-autonomous fp16 HMMA GEMM-scatter (R12/R15 configuration,
// UNCHANGED — 93us, at the structural floor for this decomposition).
//   Block = 2 tiles x 128 pairs. Warp w owns rows [32w, 32w+32) of each tile,
//   private A buffers, ONE block barrier total (for the shared B tile).
// ---------------------------------------------------------------------------
__global__ __launch_bounds__(NTHREADS, 4) void conv3d_tc_kernel(
    const int*   __restrict__ imap,       // [KVOL, PPK]
    const int*   __restrict__ omap,       // [KVOL, PPK]
    float*       __restrict__ out)        // [NVOX, COUT]
{
    extern __shared__ __align__(128) char smem[];
    const uint32_t smem_base = smem_u32(smem);
    const int tid = threadIdx.x;
    const int w = tid >> 5, l = tid & 31;
    const int k  = blockIdx.y;
    const int p0 = blockIdx.x * (128 * TILES);

    const uint32_t abuf0 = smem_base + SM_A0 + w * 4096;
    const uint32_t abuf1 = smem_base + SM_A1 + w * 4096;
    const int* imap_base = imap + k * PPK + p0 + 32 * w;

    // ---- group 0: B staging + warp's tile-0 gather ----
    {
        const char* bh = (const char*)(g_Wh + (size_t)k * COUT * CIN);
        #pragma unroll
        for (int i = 0; i < 4; i++) {
            const int u = tid + i * NTHREADS;
            const int n = u >> 3, c = u & 7;
            const uint32_t off = n * 128 + ((c ^ (n & 7)) << 4);
            CP_ASYNC_16(smem_base + SM_B + off, bh + u * 16);
        }
        gather32_async(abuf0, imap_base, l);
        CP_COMMIT();
    }
    // ---- group 1: warp's tile-1 gather ----
    gather32_async(abuf1, imap_base + 128, l);
    CP_COMMIT();

    // ---- per-lane ldmatrix address components (warp-local rows) ----
    const int lr = l & 7;
    const int rAl = ((l >> 3) & 1) * 8 + lr;     // local A row, t=0 (+16 for t=1)
    const int gA  = l >> 4;
    const int sA  = rAl & 7;                     // (+16 leaves &7 invariant)
    const int nB  = 8 * (l >> 4) + lr;
    const int gB  = (l >> 3) & 1;
    const int sB  = nB & 7;
    const int gid = l >> 2, tig = l & 3;

    // wait for group 0 (B + own tile 0), then ONE barrier so B (written by all
    // warps) is visible; no further block syncs — warps free-run.
    CP_WAIT(1);
    __syncthreads();

    #pragma unroll
    for (int t = 0; t < TILES; t++) {
        const uint32_t abuf = t ? abuf1 : abuf0;
        if (t == 1) CP_WAIT(0);                  // own tile-1 gather done

        // omap rows for this tile (consumed at scatter, hidden by MMA)
        int orow[2][2];
        {
            const int obase = k * PPK + p0 + 128 * t + 32 * w + gid;
            #pragma unroll
            for (int tt = 0; tt < 2; tt++)
                #pragma unroll
                for (int h = 0; h < 2; h++)
                    orow[tt][h] = __ldg(omap + obase + 16 * tt + 8 * h);
        }

        float d[2][8][4];
        #pragma unroll
        for (int tt = 0; tt < 2; tt++)
            #pragma unroll
            for (int j = 0; j < 8; j++)
                #pragma unroll
                for (int x = 0; x < 4; x++)
                    d[tt][j][x] = 0.0f;

        // ---- K loop: 4 x k16 steps ----
        #pragma unroll
        for (int ks = 0; ks < 4; ks++) {
            const int kcA = 2 * ks + gA;
            const int kcB = 2 * ks + gB;
            const uint32_t offA  = rAl * 128 + ((kcA ^ sA) << 4);
            const uint32_t offB0 = nB * 128 + ((kcB ^ sB) << 4);

            uint32_t a[2][4];
            ldsm_x4(a[0], abuf + offA);
            ldsm_x4(a[1], abuf + offA + 16 * 128);

            uint32_t b[8][2];
            #pragma unroll
            for (int jj = 0; jj < 4; jj++) {
                uint32_t rr[4];
                ldsm_x4(rr, smem_base + SM_B + offB0 + jj * 16 * 128);
                b[2 * jj][0] = rr[0]; b[2 * jj][1] = rr[1];
                b[2 * jj + 1][0] = rr[2]; b[2 * jj + 1][1] = rr[3];
            }

            #pragma unroll
            for (int tt = 0; tt < 2; tt++)
                #pragma unroll
                for (int j = 0; j < 8; j++)
                    mma_fp16(d[tt][j], a[tt], b[j]);
        }

        // ---- scatter-add epilogue: red.v4 straight from fragments ----
        #pragma unroll
        for (int tt = 0; tt < 2; tt++) {
            #pragma unroll
            for (int h = 0; h < 2; h++) {
                float* dst = out + (size_t)orow[tt][h] * COUT + 4 * tig;
                #pragma unroll
                for (int jp = 0; jp < 4; jp++)
                    red_add_v4(dst + 16 * jp,
                               d[tt][2 * jp][2 * h],     d[tt][2 * jp][2 * h + 1],
                               d[tt][2 * jp + 1][2 * h], d[tt][2 * jp + 1][2 * h + 1]);
            }
        }
    }
}

// ---------------------------------------------------------------------------
extern "C" void kernel_launch(void* const* d_in, const int* in_sizes, int n_in,
                              void* d_out, int out_size) {
    const float* in_feats = (const float*)d_in[0];
    const float* weights  = (const float*)d_in[1];
    const float* bias     = (const float*)d_in[2];
    const int*   imap     = (const int*)d_in[3];
    const int*   omap     = (const int*)d_in[4];
    float*       out      = (float*)d_out;

    cudaFuncSetAttribute(conv3d_tc_kernel,
                         cudaFuncAttributeMaxDynamicSharedMemorySize, SM_TOTAL);

    // 2M float4 total, 4 per thread, 256 threads -> 2048 blocks
    init_prep_kernel<<<NVOX * CIN / 4 / (256 * 4), 256>>>(
        (float4*)out, (const float4*)bias, (const float4*)in_feats, weights);

    dim3 grid(PPK / 128 / TILES, KVOL);
    conv3d_tc_kernel<<<grid, NTHREADS, SM_TOTAL>>>(imap, omap, out);
}